// round 6
// baseline (speedup 1.0000x reference)
#include <cuda_runtime.h>
#include <math.h>

// Problem constants
#define BATCH 4
#define MPAR  64
#define N2  512
#define N1  2048
#define N0  8192
#define C2  256
#define C1  128
#define C0  64

#define NT1 (BATCH * N1)          // 8192
#define NT0 (BATCH * N0)          // 32768
#define KD1 (C2 + C1)             // 384
#define H1  256
#define O1  128
#define KD2 (O1 + C0)             // 192
#define H2  128
#define O2  64

// -------- scratch (referenced ONLY from device code) --------
__device__ float g_xcat1[NT1 * KD1];
__device__ float g_x1   [NT1 * O1];
__device__ float g_xcat2[NT0 * KD2];
__device__ int   g_idx1 [NT1 * 3];
__device__ float g_w1   [NT1 * 3];
__device__ int   g_idx2 [NT0 * 3];
__device__ float g_w2   [NT0 * 3];
__device__ float g_p0   [BATCH * O1];
__device__ float g_p1   [BATCH * O2];

__device__ __forceinline__ float ftanh(float x) {
    float e = __expf(2.0f * x);
    return 1.0f - __fdividef(2.0f, e + 1.0f);
}

// -------- par branch --------
__global__ void par_kernel(const float* __restrict__ par,
                           const float* __restrict__ Wp0, const float* __restrict__ bp0,
                           const float* __restrict__ Wp1, const float* __restrict__ bp1)
{
    int j = threadIdx.x;  // 0..127
    #pragma unroll
    for (int b = 0; b < BATCH; b++) {
        float a0 = 0.0f;
        #pragma unroll 8
        for (int m = 0; m < MPAR; m++)
            a0 = fmaf(par[b * MPAR + m], Wp0[m * O1 + j], a0);
        g_p0[b * O1 + j] = ftanh(a0 + bp0[j]);
        if (j < O2) {
            float a1 = 0.0f;
            #pragma unroll 8
            for (int m = 0; m < MPAR; m++)
                a1 = fmaf(par[b * MPAR + m], Wp1[m * O2 + j], a1);
            g_p1[b * O2 + j] = ftanh(a1 + bp1[j]);
        }
    }
}

// -------- KNN (k=3) --------
template<int LAYER>
__global__ __launch_bounds__(128) void knn_kernel(const float* __restrict__ pos_src,
                                                  const float* __restrict__ pos_tgt)
{
    constexpr int NS  = (LAYER == 1) ? N2 : N1;
    constexpr int TPB = (LAYER == 1) ? N1 : N0;
    constexpr int BLK = 128;
    __shared__ float sp[NS * 3];

    int* __restrict__ idx_out  = (LAYER == 1) ? g_idx1 : g_idx2;
    float* __restrict__ w_out  = (LAYER == 1) ? g_w1   : g_w2;

    const int bpb = TPB / BLK;
    const int b   = blockIdx.x / bpb;
    const int t0  = (blockIdx.x % bpb) * BLK;
    const float* ps = pos_src + (size_t)b * NS * 3;
    for (int i = threadIdx.x; i < NS * 3; i += BLK) sp[i] = ps[i];
    __syncthreads();

    const int gt = b * TPB + t0 + threadIdx.x;
    const float px = pos_tgt[gt * 3 + 0];
    const float py = pos_tgt[gt * 3 + 1];
    const float pz = pos_tgt[gt * 3 + 2];

    float d0 = 3.4e38f, d1 = 3.4e38f, d2 = 3.4e38f;
    int   i0 = 0, i1 = 0, i2 = 0;

    #pragma unroll 4
    for (int s = 0; s < NS; s++) {
        float dx = px - sp[s * 3 + 0];
        float dy = py - sp[s * 3 + 1];
        float dz = pz - sp[s * 3 + 2];
        float d  = fmaf(dx, dx, fmaf(dy, dy, dz * dz));
        if (d < d2) {
            if (d < d1) {
                d2 = d1; i2 = i1;
                if (d < d0) { d1 = d0; i1 = i0; d0 = d; i0 = s; }
                else        { d1 = d;  i1 = s; }
            } else { d2 = d; i2 = s; }
        }
    }

    const int base = b * NS;
    idx_out[gt * 3 + 0] = base + i0;
    idx_out[gt * 3 + 1] = base + i1;
    idx_out[gt * 3 + 2] = base + i2;
    w_out[gt * 3 + 0] = __fdividef(1.0f, fmaxf(d0, 1e-16f));
    w_out[gt * 3 + 1] = __fdividef(1.0f, fmaxf(d1, 1e-16f));
    w_out[gt * 3 + 2] = __fdividef(1.0f, fmaxf(d2, 1e-16f));
}

// -------- interpolate + concat, warp-per-target --------
template<int LAYER>
__global__ __launch_bounds__(128) void interp_concat_kernel(const float* __restrict__ xsrc_arg,
                                                            const float* __restrict__ xskip)
{
    constexpr int C  = (LAYER == 1) ? C2 : O1;
    constexpr int CS = (LAYER == 1) ? C1 : C0;
    constexpr int LD = C + CS;

    const float* __restrict__ xsrc = (LAYER == 1) ? xsrc_arg : g_x1;
    const int*   __restrict__ idx  = (LAYER == 1) ? g_idx1 : g_idx2;
    const float* __restrict__ w    = (LAYER == 1) ? g_w1   : g_w2;
    float*       __restrict__ out  = (LAYER == 1) ? g_xcat1 : g_xcat2;

    const int t    = (blockIdx.x * blockDim.x + threadIdx.x) >> 5;
    const int lane = threadIdx.x & 31;

    const int j0 = idx[t * 3 + 0], j1 = idx[t * 3 + 1], j2 = idx[t * 3 + 2];
    float w0 = w[t * 3 + 0], w1 = w[t * 3 + 1], w2 = w[t * 3 + 2];
    const float inv = __fdividef(1.0f, w0 + w1 + w2);
    w0 *= inv; w1 *= inv; w2 *= inv;

    const float* r0 = xsrc + (size_t)j0 * C;
    const float* r1 = xsrc + (size_t)j1 * C;
    const float* r2 = xsrc + (size_t)j2 * C;
    float* orow = out + (size_t)t * LD;

    #pragma unroll
    for (int c = lane; c < C; c += 32)
        orow[c] = fmaf(w0, r0[c], fmaf(w1, r1[c], w2 * r2[c]));
    #pragma unroll
    for (int c = lane; c < CS; c += 32)
        orow[C + c] = xskip[(size_t)t * CS + c];
}

// -------- fused 2-layer MLP + par scale, register-prefetch weight staging --------
// 128 threads, 32-row tile, thread tile 8 rows x (H/32 | O/32) cols.
// Weight tile t+1 is loaded into registers while tile t is computed from smem.
// Scratch globals selected inside device code (host must not take their address).
template<int LAYER>
__global__ __launch_bounds__(128) void mlp_kernel(
    const float* __restrict__ Wa, const float* __restrict__ ba,
    const float* __restrict__ Wb, const float* __restrict__ bb,
    float* __restrict__ out_arg)
{
    constexpr int KD  = (LAYER == 1) ? KD1 : KD2;   // 384 / 192
    constexpr int H   = (LAYER == 1) ? H1  : H2;    // 256 / 128
    constexpr int O   = (LAYER == 1) ? O1  : O2;    // 128 / 64
    constexpr bool PLAIN = (LAYER == 2);
    constexpr int RPB = (LAYER == 1) ? N1 : N0;
    constexpr int R   = 32;
    constexpr int BK  = 16;
    constexpr int CT1 = H / 32;
    constexpr int CT2 = O / 32;
    constexpr int RT  = 8;
    constexpr int KT1 = KD / BK;
    constexpr int KT2 = H / BK;
    constexpr int W1R = BK * H / 512;   // float4 per thread, phase-1 tile
    constexpr int W2R = BK * O / 512;   // float4 per thread, phase-2 tile

    extern __shared__ float smem[];
    float* xs = smem;                   // R*KD
    float* hs = smem + R * KD;          // R*H
    float* ws = hs + R * H;             // BK*H (phase-2 uses first BK*O)

    const float* __restrict__ xin  = (LAYER == 1) ? g_xcat1 : g_xcat2;
    const float* __restrict__ p    = (LAYER == 1) ? g_p0 : g_p1;
    float*       __restrict__ outp = (LAYER == 1) ? g_x1 : out_arg;

    const int tid  = threadIdx.x;
    const int tx   = tid & 31;
    const int ty   = tid >> 5;          // 0..3
    const int row0 = blockIdx.x * R;

    // stage X rows (plain copy, coalesced, conflict-free)
    {
        const float4* xsrc = reinterpret_cast<const float4*>(xin + (size_t)row0 * KD);
        float4* dst = reinterpret_cast<float4*>(xs);
        #pragma unroll 4
        for (int i = tid; i < R * KD / 4; i += 128) dst[i] = xsrc[i];
    }

    // preload Wa tile 0 into registers
    const float4* Wa4 = reinterpret_cast<const float4*>(Wa);
    float4* ws4 = reinterpret_cast<float4*>(ws);
    float4 wreg[W1R];
    #pragma unroll
    for (int j = 0; j < W1R; j++) wreg[j] = Wa4[j * 128 + tid];

    __syncthreads();   // xs visible to all

    // ---- phase 1 ----
    float acc[RT][CT1];
    #pragma unroll
    for (int r = 0; r < RT; r++)
        #pragma unroll
        for (int c = 0; c < CT1; c++) acc[r][c] = 0.0f;

    for (int t = 0; t < KT1; t++) {
        #pragma unroll
        for (int j = 0; j < W1R; j++) ws4[j * 128 + tid] = wreg[j];
        __syncthreads();
        if (t + 1 < KT1) {
            #pragma unroll
            for (int j = 0; j < W1R; j++)
                wreg[j] = Wa4[(t + 1) * (BK * H / 4) + j * 128 + tid];
        }
        const float* xrow = xs + (ty * RT) * KD + t * BK;
        #pragma unroll 4
        for (int k = 0; k < BK; k++) {
            float wv[CT1];
            #pragma unroll
            for (int c = 0; c < CT1; c++) wv[c] = ws[k * H + tx + 32 * c];
            #pragma unroll
            for (int r = 0; r < RT; r++) {
                float xv = xrow[r * KD + k];
                #pragma unroll
                for (int c = 0; c < CT1; c++)
                    acc[r][c] = fmaf(xv, wv[c], acc[r][c]);
            }
        }
        __syncthreads();
    }

    // preload Wb tile 0 while doing the tanh epilogue
    const float4* Wb4 = reinterpret_cast<const float4*>(Wb);
    float4 wreg2[W2R];
    #pragma unroll
    for (int j = 0; j < W2R; j++) wreg2[j] = Wb4[j * 128 + tid];

    // tanh + write hidden into smem
    #pragma unroll
    for (int c = 0; c < CT1; c++) {
        float bj = ba[tx + 32 * c];
        #pragma unroll
        for (int r = 0; r < RT; r++)
            hs[(ty * RT + r) * H + tx + 32 * c] = ftanh(acc[r][c] + bj);
    }

    // ---- phase 2 ----
    float acc2[RT][CT2];
    #pragma unroll
    for (int r = 0; r < RT; r++)
        #pragma unroll
        for (int c = 0; c < CT2; c++) acc2[r][c] = 0.0f;

    for (int t = 0; t < KT2; t++) {
        #pragma unroll
        for (int j = 0; j < W2R; j++) ws4[j * 128 + tid] = wreg2[j];
        __syncthreads();   // first iter also fences hs writes -> hs reads
        if (t + 1 < KT2) {
            #pragma unroll
            for (int j = 0; j < W2R; j++)
                wreg2[j] = Wb4[(t + 1) * (BK * O / 4) + j * 128 + tid];
        }
        const float* hrow = hs + (ty * RT) * H + t * BK;
        #pragma unroll 4
        for (int k = 0; k < BK; k++) {
            float wv[CT2];
            #pragma unroll
            for (int c = 0; c < CT2; c++) wv[c] = ws[k * O + tx + 32 * c];
            #pragma unroll
            for (int r = 0; r < RT; r++) {
                float hv = hrow[r * H + k];
                #pragma unroll
                for (int c = 0; c < CT2; c++)
                    acc2[r][c] = fmaf(hv, wv[c], acc2[r][c]);
            }
        }
        __syncthreads();
    }

    const int bat = row0 / RPB;
    #pragma unroll
    for (int c = 0; c < CT2; c++) {
        float bias = bb[tx + 32 * c];
        float pv   = p[bat * O + tx + 32 * c];
        #pragma unroll
        for (int r = 0; r < RT; r++) {
            float y = acc2[r][c] + bias;
            if (!PLAIN) y = ftanh(y);
            outp[(size_t)(row0 + ty * RT + r) * O + tx + 32 * c] = y * pv;
        }
    }
}

// -------- tail: append pos_skip_l0 and batch_skip_l0 (as float) --------
__global__ void tail_kernel(const float* __restrict__ pos0,
                            const int* __restrict__ bat0,
                            float* __restrict__ out)
{
    const int i = blockIdx.x * blockDim.x + threadIdx.x;
    const int NP = NT0 * 3;
    if (i < NP)
        out[(size_t)NT0 * O2 + i] = pos0[i];
    else if (i < NP + NT0)
        out[(size_t)NT0 * O2 + i] = (float)bat0[i - NP];
}

extern "C" void kernel_launch(void* const* d_in, const int* in_sizes, int n_in,
                              void* d_out, int out_size) {
    const float* par          = (const float*)d_in[0];
    const float* x            = (const float*)d_in[1];
    const float* pos          = (const float*)d_in[2];
    const float* x_skip_l1    = (const float*)d_in[4];
    const float* pos_skip_l1  = (const float*)d_in[5];
    const float* x_skip_l0    = (const float*)d_in[7];
    const float* pos_skip_l0  = (const float*)d_in[8];
    const int*   batch_skip_l0= (const int*)  d_in[9];
    const float* W0a = (const float*)d_in[10];
    const float* b0a = (const float*)d_in[11];
    const float* W0b = (const float*)d_in[12];
    const float* b0b = (const float*)d_in[13];
    const float* Wp0 = (const float*)d_in[14];
    const float* bp0 = (const float*)d_in[15];
    const float* W1a = (const float*)d_in[16];
    const float* b1a = (const float*)d_in[17];
    const float* W1b = (const float*)d_in[18];
    const float* b1b = (const float*)d_in[19];
    const float* Wp1 = (const float*)d_in[20];
    const float* bp1 = (const float*)d_in[21];
    float* out = (float*)d_out;

    const int smem1 = (32 * KD1 + 32 * H1 + 16 * H1) * sizeof(float);  // 98304
    const int smem2 = (32 * KD2 + 32 * H2 + 16 * H2) * sizeof(float);  // 49152
    cudaFuncSetAttribute(mlp_kernel<1>, cudaFuncAttributeMaxDynamicSharedMemorySize, smem1);
    cudaFuncSetAttribute(mlp_kernel<2>, cudaFuncAttributeMaxDynamicSharedMemorySize, smem2);

    par_kernel<<<1, 128>>>(par, Wp0, bp0, Wp1, bp1);

    knn_kernel<1><<<NT1 / 128, 128>>>(pos, pos_skip_l1);
    interp_concat_kernel<1><<<NT1 / 4, 128>>>(x, x_skip_l1);
    mlp_kernel<1><<<NT1 / 32, 128, smem1>>>(W0a, b0a, W0b, b0b, nullptr);

    knn_kernel<2><<<NT0 / 128, 128>>>(pos_skip_l1, pos_skip_l0);
    interp_concat_kernel<2><<<NT0 / 4, 128>>>(nullptr, x_skip_l0);
    mlp_kernel<2><<<NT0 / 32, 128, smem2>>>(W1a, b1a, W1b, b1b, out);

    const long long full = (long long)NT0 * O2 + (long long)NT0 * 3 + NT0;
    if ((long long)out_size >= full) {
        tail_kernel<<<(NT0 * 3 + NT0 + 255) / 256, 256>>>(pos_skip_l0, batch_skip_l0, out);
    }
}

// round 7
// speedup vs baseline: 1.5867x; 1.5867x over previous
#include <cuda_runtime.h>
#include <math.h>

// Problem constants
#define BATCH 4
#define MPAR  64
#define N2  512
#define N1  2048
#define N0  8192
#define C2  256
#define C1  128
#define C0  64

#define NT1 (BATCH * N1)          // 8192
#define NT0 (BATCH * N0)          // 32768
#define KD1 (C2 + C1)             // 384
#define H1  256
#define O1  128
#define KD2 (O1 + C0)             // 192
#define H2  128
#define O2  64

// -------- scratch (referenced ONLY from device code) --------
__device__ float g_xcat1[NT1 * KD1];
__device__ float g_x1   [NT1 * O1];
__device__ float g_xcat2[NT0 * KD2];
__device__ int   g_idx1 [NT1 * 3];
__device__ float g_w1   [NT1 * 3];
__device__ int   g_idx2 [NT0 * 3];
__device__ float g_w2   [NT0 * 3];
__device__ float g_p0   [BATCH * O1];
__device__ float g_p1   [BATCH * O2];

__device__ __forceinline__ float ftanh(float x) {
    float e = __expf(2.0f * x);
    return 1.0f - __fdividef(2.0f, e + 1.0f);
}

// -------- par branch --------
__global__ void par_kernel(const float* __restrict__ par,
                           const float* __restrict__ Wp0, const float* __restrict__ bp0,
                           const float* __restrict__ Wp1, const float* __restrict__ bp1)
{
    int j = threadIdx.x;  // 0..127
    #pragma unroll
    for (int b = 0; b < BATCH; b++) {
        float a0 = 0.0f;
        #pragma unroll 8
        for (int m = 0; m < MPAR; m++)
            a0 = fmaf(par[b * MPAR + m], Wp0[m * O1 + j], a0);
        g_p0[b * O1 + j] = ftanh(a0 + bp0[j]);
        if (j < O2) {
            float a1 = 0.0f;
            #pragma unroll 8
            for (int m = 0; m < MPAR; m++)
                a1 = fmaf(par[b * MPAR + m], Wp1[m * O2 + j], a1);
            g_p1[b * O2 + j] = ftanh(a1 + bp1[j]);
        }
    }
}

// -------- KNN (k=3) --------
template<int LAYER>
__global__ __launch_bounds__(128) void knn_kernel(const float* __restrict__ pos_src,
                                                  const float* __restrict__ pos_tgt)
{
    constexpr int NS  = (LAYER == 1) ? N2 : N1;
    constexpr int TPB = (LAYER == 1) ? N1 : N0;
    constexpr int BLK = 128;
    __shared__ float sp[NS * 3];

    int* __restrict__ idx_out  = (LAYER == 1) ? g_idx1 : g_idx2;
    float* __restrict__ w_out  = (LAYER == 1) ? g_w1   : g_w2;

    const int bpb = TPB / BLK;
    const int b   = blockIdx.x / bpb;
    const int t0  = (blockIdx.x % bpb) * BLK;
    const float* ps = pos_src + (size_t)b * NS * 3;
    for (int i = threadIdx.x; i < NS * 3; i += BLK) sp[i] = ps[i];
    __syncthreads();

    const int gt = b * TPB + t0 + threadIdx.x;
    const float px = pos_tgt[gt * 3 + 0];
    const float py = pos_tgt[gt * 3 + 1];
    const float pz = pos_tgt[gt * 3 + 2];

    float d0 = 3.4e38f, d1 = 3.4e38f, d2 = 3.4e38f;
    int   i0 = 0, i1 = 0, i2 = 0;

    #pragma unroll 4
    for (int s = 0; s < NS; s++) {
        float dx = px - sp[s * 3 + 0];
        float dy = py - sp[s * 3 + 1];
        float dz = pz - sp[s * 3 + 2];
        float d  = fmaf(dx, dx, fmaf(dy, dy, dz * dz));
        if (d < d2) {
            if (d < d1) {
                d2 = d1; i2 = i1;
                if (d < d0) { d1 = d0; i1 = i0; d0 = d; i0 = s; }
                else        { d1 = d;  i1 = s; }
            } else { d2 = d; i2 = s; }
        }
    }

    const int base = b * NS;
    idx_out[gt * 3 + 0] = base + i0;
    idx_out[gt * 3 + 1] = base + i1;
    idx_out[gt * 3 + 2] = base + i2;
    w_out[gt * 3 + 0] = __fdividef(1.0f, fmaxf(d0, 1e-16f));
    w_out[gt * 3 + 1] = __fdividef(1.0f, fmaxf(d1, 1e-16f));
    w_out[gt * 3 + 2] = __fdividef(1.0f, fmaxf(d2, 1e-16f));
}

// -------- interpolate + concat, warp-per-target --------
template<int LAYER>
__global__ __launch_bounds__(128) void interp_concat_kernel(const float* __restrict__ xsrc_arg,
                                                            const float* __restrict__ xskip)
{
    constexpr int C  = (LAYER == 1) ? C2 : O1;
    constexpr int CS = (LAYER == 1) ? C1 : C0;
    constexpr int LD = C + CS;

    const float* __restrict__ xsrc = (LAYER == 1) ? xsrc_arg : g_x1;
    const int*   __restrict__ idx  = (LAYER == 1) ? g_idx1 : g_idx2;
    const float* __restrict__ w    = (LAYER == 1) ? g_w1   : g_w2;
    float*       __restrict__ out  = (LAYER == 1) ? g_xcat1 : g_xcat2;

    const int t    = (blockIdx.x * blockDim.x + threadIdx.x) >> 5;
    const int lane = threadIdx.x & 31;

    const int j0 = idx[t * 3 + 0], j1 = idx[t * 3 + 1], j2 = idx[t * 3 + 2];
    float w0 = w[t * 3 + 0], w1 = w[t * 3 + 1], w2 = w[t * 3 + 2];
    const float inv = __fdividef(1.0f, w0 + w1 + w2);
    w0 *= inv; w1 *= inv; w2 *= inv;

    const float* r0 = xsrc + (size_t)j0 * C;
    const float* r1 = xsrc + (size_t)j1 * C;
    const float* r2 = xsrc + (size_t)j2 * C;
    float* orow = out + (size_t)t * LD;

    #pragma unroll
    for (int c = lane; c < C; c += 32)
        orow[c] = fmaf(w0, r0[c], fmaf(w1, r1[c], w2 * r2[c]));
    #pragma unroll
    for (int c = lane; c < CS; c += 32)
        orow[C + c] = xskip[(size_t)t * CS + c];
}

// -------- fused 2-layer MLP + par scale --------
// 256 threads, 8 warps. Layer 1: 32 rows, 4 row-warps x 2 col-warps.
// Layer 2: 64 rows, 8 row-warps. Register-prefetch weight staging, BK=16.
template<int LAYER>
__global__ __launch_bounds__(256, 2) void mlp_kernel(
    const float* __restrict__ Wa, const float* __restrict__ ba,
    const float* __restrict__ Wb, const float* __restrict__ bb,
    float* __restrict__ out_arg)
{
    constexpr int KD  = (LAYER == 1) ? KD1 : KD2;   // 384 / 192
    constexpr int H   = (LAYER == 1) ? H1  : H2;    // 256 / 128
    constexpr int O   = (LAYER == 1) ? O1  : O2;    // 128 / 64
    constexpr bool PLAIN = (LAYER == 2);
    constexpr int RPB = (LAYER == 1) ? N1 : N0;
    constexpr int WC  = (LAYER == 1) ? 2 : 1;       // col-warp groups
    constexpr int R   = 8 * (8 / WC);               // 32 / 64 rows per block
    constexpr int RT  = 8;                          // rows per thread
    constexpr int BK  = 16;
    constexpr int CT1 = H / (32 * WC);              // 4 / 4
    constexpr int CT2 = O / (32 * WC);              // 2 / 2
    constexpr int KT1 = KD / BK;
    constexpr int KT2 = H / BK;
    constexpr int W1R = BK * H / 1024;              // float4/thread, phase-1 tile (4/2)
    constexpr int W2R = BK * O / 1024;              // float4/thread, phase-2 tile (2/1)

    extern __shared__ float smem[];
    float* xs = smem;                   // R*KD
    float* hs = smem + R * KD;          // R*H
    float* ws = hs + R * H;             // BK*H

    const float* __restrict__ xin  = (LAYER == 1) ? g_xcat1 : g_xcat2;
    const float* __restrict__ p    = (LAYER == 1) ? g_p0 : g_p1;
    float*       __restrict__ outp = (LAYER == 1) ? g_x1 : out_arg;

    const int tid  = threadIdx.x;
    const int tx   = tid & 31;
    const int w    = tid >> 5;            // 0..7
    const int rw   = w / WC;              // row-warp
    const int cw   = w % WC;              // col-warp
    const int cb1  = cw * (H / WC) + tx;  // phase-1 col base
    const int cb2  = cw * (O / WC) + tx;  // phase-2 col base
    const int row0 = blockIdx.x * R;

    // stage X rows (coalesced float4)
    {
        const float4* xsrc = reinterpret_cast<const float4*>(xin + (size_t)row0 * KD);
        float4* dst = reinterpret_cast<float4*>(xs);
        #pragma unroll 4
        for (int i = tid; i < R * KD / 4; i += 256) dst[i] = xsrc[i];
    }

    // preload Wa tile 0 into registers
    const float4* Wa4 = reinterpret_cast<const float4*>(Wa);
    float4* ws4 = reinterpret_cast<float4*>(ws);
    float4 wreg[W1R];
    #pragma unroll
    for (int j = 0; j < W1R; j++) wreg[j] = Wa4[j * 256 + tid];

    __syncthreads();   // xs visible

    // ---- phase 1 ----
    float acc[RT][CT1];
    #pragma unroll
    for (int r = 0; r < RT; r++)
        #pragma unroll
        for (int c = 0; c < CT1; c++) acc[r][c] = 0.0f;

    for (int t = 0; t < KT1; t++) {
        #pragma unroll
        for (int j = 0; j < W1R; j++) ws4[j * 256 + tid] = wreg[j];
        __syncthreads();
        if (t + 1 < KT1) {
            #pragma unroll
            for (int j = 0; j < W1R; j++)
                wreg[j] = Wa4[(t + 1) * (BK * H / 4) + j * 256 + tid];
        }
        const float* xrow = xs + (rw * RT) * KD + t * BK;
        #pragma unroll 4
        for (int k = 0; k < BK; k++) {
            float wv[CT1];
            #pragma unroll
            for (int c = 0; c < CT1; c++) wv[c] = ws[k * H + cb1 + 32 * c];
            #pragma unroll
            for (int r = 0; r < RT; r++) {
                float xv = xrow[r * KD + k];
                #pragma unroll
                for (int c = 0; c < CT1; c++)
                    acc[r][c] = fmaf(xv, wv[c], acc[r][c]);
            }
        }
        __syncthreads();
    }

    // preload Wb tile 0 during tanh epilogue
    const float4* Wb4 = reinterpret_cast<const float4*>(Wb);
    float4 wreg2[W2R];
    #pragma unroll
    for (int j = 0; j < W2R; j++) wreg2[j] = Wb4[j * 256 + tid];

    // tanh + write hidden into smem
    #pragma unroll
    for (int c = 0; c < CT1; c++) {
        float bj = ba[cb1 + 32 * c];
        #pragma unroll
        for (int r = 0; r < RT; r++)
            hs[(rw * RT + r) * H + cb1 + 32 * c] = ftanh(acc[r][c] + bj);
    }

    // ---- phase 2 ----
    float acc2[RT][CT2];
    #pragma unroll
    for (int r = 0; r < RT; r++)
        #pragma unroll
        for (int c = 0; c < CT2; c++) acc2[r][c] = 0.0f;

    for (int t = 0; t < KT2; t++) {
        #pragma unroll
        for (int j = 0; j < W2R; j++) ws4[j * 256 + tid] = wreg2[j];
        __syncthreads();   // first iter also fences hs writes -> hs reads
        if (t + 1 < KT2) {
            #pragma unroll
            for (int j = 0; j < W2R; j++)
                wreg2[j] = Wb4[(t + 1) * (BK * O / 4) + j * 256 + tid];
        }
        const float* hrow = hs + (rw * RT) * H + t * BK;
        #pragma unroll 4
        for (int k = 0; k < BK; k++) {
            float wv[CT2];
            #pragma unroll
            for (int c = 0; c < CT2; c++) wv[c] = ws[k * O + cb2 + 32 * c];
            #pragma unroll
            for (int r = 0; r < RT; r++) {
                float hv = hrow[r * H + k];
                #pragma unroll
                for (int c = 0; c < CT2; c++)
                    acc2[r][c] = fmaf(hv, wv[c], acc2[r][c]);
            }
        }
        __syncthreads();
    }

    const int bat = row0 / RPB;
    #pragma unroll
    for (int c = 0; c < CT2; c++) {
        float bias = bb[cb2 + 32 * c];
        float pv   = p[bat * O + cb2 + 32 * c];
        #pragma unroll
        for (int r = 0; r < RT; r++) {
            float y = acc2[r][c] + bias;
            if (!PLAIN) y = ftanh(y);
            outp[(size_t)(row0 + rw * RT + r) * O + cb2 + 32 * c] = y * pv;
        }
    }
}

// -------- tail: append pos_skip_l0 and batch_skip_l0 (as float) --------
__global__ void tail_kernel(const float* __restrict__ pos0,
                            const int* __restrict__ bat0,
                            float* __restrict__ out)
{
    const int i = blockIdx.x * blockDim.x + threadIdx.x;
    const int NP = NT0 * 3;
    if (i < NP)
        out[(size_t)NT0 * O2 + i] = pos0[i];
    else if (i < NP + NT0)
        out[(size_t)NT0 * O2 + i] = (float)bat0[i - NP];
}

extern "C" void kernel_launch(void* const* d_in, const int* in_sizes, int n_in,
                              void* d_out, int out_size) {
    const float* par          = (const float*)d_in[0];
    const float* x            = (const float*)d_in[1];
    const float* pos          = (const float*)d_in[2];
    const float* x_skip_l1    = (const float*)d_in[4];
    const float* pos_skip_l1  = (const float*)d_in[5];
    const float* x_skip_l0    = (const float*)d_in[7];
    const float* pos_skip_l0  = (const float*)d_in[8];
    const int*   batch_skip_l0= (const int*)  d_in[9];
    const float* W0a = (const float*)d_in[10];
    const float* b0a = (const float*)d_in[11];
    const float* W0b = (const float*)d_in[12];
    const float* b0b = (const float*)d_in[13];
    const float* Wp0 = (const float*)d_in[14];
    const float* bp0 = (const float*)d_in[15];
    const float* W1a = (const float*)d_in[16];
    const float* b1a = (const float*)d_in[17];
    const float* W1b = (const float*)d_in[18];
    const float* b1b = (const float*)d_in[19];
    const float* Wp1 = (const float*)d_in[20];
    const float* bp1 = (const float*)d_in[21];
    float* out = (float*)d_out;

    const int smem1 = (32 * KD1 + 32 * H1 + 16 * H1) * sizeof(float);  // 98304
    const int smem2 = (64 * KD2 + 64 * H2 + 16 * H2) * sizeof(float);  // 90112
    cudaFuncSetAttribute(mlp_kernel<1>, cudaFuncAttributeMaxDynamicSharedMemorySize, smem1);
    cudaFuncSetAttribute(mlp_kernel<2>, cudaFuncAttributeMaxDynamicSharedMemorySize, smem2);

    par_kernel<<<1, 128>>>(par, Wp0, bp0, Wp1, bp1);

    knn_kernel<1><<<NT1 / 128, 128>>>(pos, pos_skip_l1);
    interp_concat_kernel<1><<<NT1 / 4, 128>>>(x, x_skip_l1);
    mlp_kernel<1><<<NT1 / 32, 256, smem1>>>(W0a, b0a, W0b, b0b, nullptr);

    knn_kernel<2><<<NT0 / 128, 128>>>(pos_skip_l1, pos_skip_l0);
    interp_concat_kernel<2><<<NT0 / 4, 128>>>(nullptr, x_skip_l0);
    mlp_kernel<2><<<NT0 / 64, 256, smem2>>>(W1a, b1a, W1b, b1b, out);

    const long long full = (long long)NT0 * O2 + (long long)NT0 * 3 + NT0;
    if ((long long)out_size >= full) {
        tail_kernel<<<(NT0 * 3 + NT0 + 255) / 256, 256>>>(pos_skip_l0, batch_skip_l0, out);
    }
}

// round 8
// speedup vs baseline: 1.7776x; 1.1203x over previous
#include <cuda_runtime.h>
#include <math.h>

// Problem constants
#define BATCH 4
#define MPAR  64
#define N2  512
#define N1  2048
#define N0  8192
#define C2  256
#define C1  128
#define C0  64

#define NT1 (BATCH * N1)          // 8192
#define NT0 (BATCH * N0)          // 32768
#define KD1 (C2 + C1)             // 384
#define H1  256
#define O1  128
#define KD2 (O1 + C0)             // 192
#define H2  128
#define O2  64

// -------- scratch (referenced ONLY from device code) --------
__device__ float g_x1   [NT1 * O1];
__device__ int   g_idx1 [NT1 * 3];
__device__ float g_w1   [NT1 * 3];
__device__ int   g_idx2 [NT0 * 3];
__device__ float g_w2   [NT0 * 3];
__device__ float g_p0   [BATCH * O1];
__device__ float g_p1   [BATCH * O2];

__device__ __forceinline__ float ftanh(float x) {
    float e = __expf(2.0f * x);
    return 1.0f - __fdividef(2.0f, e + 1.0f);
}

// -------- par branch --------
__global__ void par_kernel(const float* __restrict__ par,
                           const float* __restrict__ Wp0, const float* __restrict__ bp0,
                           const float* __restrict__ Wp1, const float* __restrict__ bp1)
{
    int j = threadIdx.x;  // 0..127
    #pragma unroll
    for (int b = 0; b < BATCH; b++) {
        float a0 = 0.0f;
        #pragma unroll 8
        for (int m = 0; m < MPAR; m++)
            a0 = fmaf(par[b * MPAR + m], Wp0[m * O1 + j], a0);
        g_p0[b * O1 + j] = ftanh(a0 + bp0[j]);
        if (j < O2) {
            float a1 = 0.0f;
            #pragma unroll 8
            for (int m = 0; m < MPAR; m++)
                a1 = fmaf(par[b * MPAR + m], Wp1[m * O2 + j], a1);
            g_p1[b * O2 + j] = ftanh(a1 + bp1[j]);
        }
    }
}

// -------- KNN (k=3): d' = |s|^2 - 2 p.s  (monotone in true distance) --------
template<int LAYER>
__global__ __launch_bounds__(128) void knn_kernel(const float* __restrict__ pos_src,
                                                  const float* __restrict__ pos_tgt)
{
    constexpr int NS  = (LAYER == 1) ? N2 : N1;
    constexpr int TPB = (LAYER == 1) ? N1 : N0;
    constexpr int BLK = 128;
    __shared__ float4 sp[NS];

    int* __restrict__ idx_out  = (LAYER == 1) ? g_idx1 : g_idx2;
    float* __restrict__ w_out  = (LAYER == 1) ? g_w1   : g_w2;

    const int bpb = TPB / BLK;
    const int b   = blockIdx.x / bpb;
    const int t0  = (blockIdx.x % bpb) * BLK;
    const float* ps = pos_src + (size_t)b * NS * 3;
    for (int i = threadIdx.x; i < NS; i += BLK) {
        float sx = ps[i * 3 + 0], sy = ps[i * 3 + 1], sz = ps[i * 3 + 2];
        sp[i] = make_float4(sx, sy, sz, fmaf(sx, sx, fmaf(sy, sy, sz * sz)));
    }
    __syncthreads();

    const int gt = b * TPB + t0 + threadIdx.x;
    const float px = pos_tgt[gt * 3 + 0];
    const float py = pos_tgt[gt * 3 + 1];
    const float pz = pos_tgt[gt * 3 + 2];
    const float nx = -2.0f * px, ny = -2.0f * py, nz = -2.0f * pz;

    float d0 = 3.4e38f, d1 = 3.4e38f, d2 = 3.4e38f;
    int   i0 = 0, i1 = 0, i2 = 0;

    #pragma unroll 4
    for (int s = 0; s < NS; s++) {
        float4 v = sp[s];
        float d = fmaf(nx, v.x, fmaf(ny, v.y, fmaf(nz, v.z, v.w)));
        if (d < d2) {
            if (d < d1) {
                d2 = d1; i2 = i1;
                if (d < d0) { d1 = d0; i1 = i0; d0 = d; i0 = s; }
                else        { d1 = d;  i1 = s; }
            } else { d2 = d; i2 = s; }
        }
    }

    // exact squared distances for the 3 winners (matches reference weights)
    float4 v0 = sp[i0], v1 = sp[i1], v2 = sp[i2];
    float dx, dy, dz;
    dx = px - v0.x; dy = py - v0.y; dz = pz - v0.z;
    float e0 = fmaf(dx, dx, fmaf(dy, dy, dz * dz));
    dx = px - v1.x; dy = py - v1.y; dz = pz - v1.z;
    float e1 = fmaf(dx, dx, fmaf(dy, dy, dz * dz));
    dx = px - v2.x; dy = py - v2.y; dz = pz - v2.z;
    float e2 = fmaf(dx, dx, fmaf(dy, dy, dz * dz));

    const int base = b * NS;
    idx_out[gt * 3 + 0] = base + i0;
    idx_out[gt * 3 + 1] = base + i1;
    idx_out[gt * 3 + 2] = base + i2;
    w_out[gt * 3 + 0] = __fdividef(1.0f, fmaxf(e0, 1e-16f));
    w_out[gt * 3 + 1] = __fdividef(1.0f, fmaxf(e1, 1e-16f));
    w_out[gt * 3 + 2] = __fdividef(1.0f, fmaxf(e2, 1e-16f));
}

// -------- fused interp + concat + 2-layer MLP + par scale --------
// 256 threads, 8 warps. Layer 1: 32 rows, 4 row-warps x 2 col-warps.
// Layer 2: 64 rows, 8 row-warps. Register-prefetch weight staging, BK=16.
// Staging gathers 3 neighbor rows (inverse-distance weighted) + skip features
// directly into smem -- no xcat global round-trip.
template<int LAYER>
__global__ __launch_bounds__(256, 2) void mlp_kernel(
    const float* __restrict__ Wa, const float* __restrict__ ba,
    const float* __restrict__ Wb, const float* __restrict__ bb,
    const float* __restrict__ xsrc_arg, const float* __restrict__ xskip,
    float* __restrict__ out_arg)
{
    constexpr int KD  = (LAYER == 1) ? KD1 : KD2;   // 384 / 192
    constexpr int H   = (LAYER == 1) ? H1  : H2;    // 256 / 128
    constexpr int O   = (LAYER == 1) ? O1  : O2;    // 128 / 64
    constexpr int C   = (LAYER == 1) ? C2  : O1;    // interp width 256 / 128
    constexpr int CS  = KD - C;                     // skip width 128 / 64
    constexpr bool PLAIN = (LAYER == 2);
    constexpr int RPB = (LAYER == 1) ? N1 : N0;
    constexpr int WC  = (LAYER == 1) ? 2 : 1;       // col-warp groups
    constexpr int R   = 8 * (8 / WC);               // 32 / 64 rows per block
    constexpr int RT  = 8;                          // rows per thread
    constexpr int BK  = 16;
    constexpr int CT1 = H / (32 * WC);              // 4
    constexpr int CT2 = O / (32 * WC);              // 2
    constexpr int KT1 = KD / BK;
    constexpr int KT2 = H / BK;
    constexpr int W1R = BK * H / 1024;              // float4/thread, phase-1 tile
    constexpr int W2R = BK * O / 1024;              // float4/thread, phase-2 tile

    extern __shared__ float smem[];
    float* xs = smem;                   // R*KD
    float* hs = smem + R * KD;          // R*H
    float* ws = hs + R * H;             // BK*H

    const float* __restrict__ xsrc = (LAYER == 1) ? xsrc_arg : g_x1;
    const int*   __restrict__ idx  = (LAYER == 1) ? g_idx1 : g_idx2;
    const float* __restrict__ wgt  = (LAYER == 1) ? g_w1   : g_w2;
    const float* __restrict__ p    = (LAYER == 1) ? g_p0 : g_p1;
    float*       __restrict__ outp = (LAYER == 1) ? g_x1 : out_arg;

    const int tid  = threadIdx.x;
    const int tx   = tid & 31;
    const int w    = tid >> 5;            // 0..7
    const int rw   = w / WC;              // row-warp
    const int cw   = w % WC;              // col-warp
    const int cb1  = cw * (H / WC) + tx;  // phase-1 col base
    const int cb2  = cw * (O / WC) + tx;  // phase-2 col base
    const int row0 = blockIdx.x * R;

    // ---- staging: interpolate + concat directly into smem (warp per row) ----
    for (int rr = w; rr < R; rr += 8) {
        const int t = row0 + rr;
        const int j0 = idx[t * 3 + 0], j1 = idx[t * 3 + 1], j2 = idx[t * 3 + 2];
        float w0 = wgt[t * 3 + 0], w1 = wgt[t * 3 + 1], w2 = wgt[t * 3 + 2];
        const float inv = __fdividef(1.0f, w0 + w1 + w2);
        w0 *= inv; w1 *= inv; w2 *= inv;

        const float4* r0 = reinterpret_cast<const float4*>(xsrc + (size_t)j0 * C);
        const float4* r1 = reinterpret_cast<const float4*>(xsrc + (size_t)j1 * C);
        const float4* r2 = reinterpret_cast<const float4*>(xsrc + (size_t)j2 * C);
        float4* xrow4 = reinterpret_cast<float4*>(xs + rr * KD);

        #pragma unroll
        for (int c = tx; c < C / 4; c += 32) {
            float4 a = r0[c], bq = r1[c], cq = r2[c];
            float4 o;
            o.x = fmaf(w0, a.x, fmaf(w1, bq.x, w2 * cq.x));
            o.y = fmaf(w0, a.y, fmaf(w1, bq.y, w2 * cq.y));
            o.z = fmaf(w0, a.z, fmaf(w1, bq.z, w2 * cq.z));
            o.w = fmaf(w0, a.w, fmaf(w1, bq.w, w2 * cq.w));
            xrow4[c] = o;
        }
        const float4* sk = reinterpret_cast<const float4*>(xskip + (size_t)t * CS);
        #pragma unroll
        for (int c = tx; c < CS / 4; c += 32)
            xrow4[C / 4 + c] = sk[c];
    }

    // preload Wa tile 0 into registers
    const float4* Wa4 = reinterpret_cast<const float4*>(Wa);
    float4* ws4 = reinterpret_cast<float4*>(ws);
    float4 wreg[W1R];
    #pragma unroll
    for (int j = 0; j < W1R; j++) wreg[j] = Wa4[j * 256 + tid];

    __syncthreads();   // xs visible

    // ---- phase 1 ----
    float acc[RT][CT1];
    #pragma unroll
    for (int r = 0; r < RT; r++)
        #pragma unroll
        for (int c = 0; c < CT1; c++) acc[r][c] = 0.0f;

    for (int t = 0; t < KT1; t++) {
        #pragma unroll
        for (int j = 0; j < W1R; j++) ws4[j * 256 + tid] = wreg[j];
        __syncthreads();
        if (t + 1 < KT1) {
            #pragma unroll
            for (int j = 0; j < W1R; j++)
                wreg[j] = Wa4[(t + 1) * (BK * H / 4) + j * 256 + tid];
        }
        const float* xrow = xs + (rw * RT) * KD + t * BK;
        #pragma unroll
        for (int k4 = 0; k4 < BK / 4; k4++) {
            float4 xv[RT];
            #pragma unroll
            for (int r = 0; r < RT; r++)
                xv[r] = *reinterpret_cast<const float4*>(xrow + r * KD + k4 * 4);
            #pragma unroll
            for (int kk = 0; kk < 4; kk++) {
                float wv[CT1];
                #pragma unroll
                for (int c = 0; c < CT1; c++) wv[c] = ws[(k4 * 4 + kk) * H + cb1 + 32 * c];
                #pragma unroll
                for (int r = 0; r < RT; r++) {
                    float xvk = (kk == 0) ? xv[r].x : (kk == 1) ? xv[r].y : (kk == 2) ? xv[r].z : xv[r].w;
                    #pragma unroll
                    for (int c = 0; c < CT1; c++)
                        acc[r][c] = fmaf(xvk, wv[c], acc[r][c]);
                }
            }
        }
        __syncthreads();
    }

    // preload Wb tile 0 during tanh epilogue
    const float4* Wb4 = reinterpret_cast<const float4*>(Wb);
    float4 wreg2[W2R];
    #pragma unroll
    for (int j = 0; j < W2R; j++) wreg2[j] = Wb4[j * 256 + tid];

    // tanh + write hidden into smem
    #pragma unroll
    for (int c = 0; c < CT1; c++) {
        float bj = ba[cb1 + 32 * c];
        #pragma unroll
        for (int r = 0; r < RT; r++)
            hs[(rw * RT + r) * H + cb1 + 32 * c] = ftanh(acc[r][c] + bj);
    }

    // ---- phase 2 ----
    float acc2[RT][CT2];
    #pragma unroll
    for (int r = 0; r < RT; r++)
        #pragma unroll
        for (int c = 0; c < CT2; c++) acc2[r][c] = 0.0f;

    for (int t = 0; t < KT2; t++) {
        #pragma unroll
        for (int j = 0; j < W2R; j++) ws4[j * 256 + tid] = wreg2[j];
        __syncthreads();   // first iter also fences hs writes -> hs reads
        if (t + 1 < KT2) {
            #pragma unroll
            for (int j = 0; j < W2R; j++)
                wreg2[j] = Wb4[(t + 1) * (BK * O / 4) + j * 256 + tid];
        }
        const float* hrow = hs + (rw * RT) * H + t * BK;
        #pragma unroll
        for (int k4 = 0; k4 < BK / 4; k4++) {
            float4 hv[RT];
            #pragma unroll
            for (int r = 0; r < RT; r++)
                hv[r] = *reinterpret_cast<const float4*>(hrow + r * H + k4 * 4);
            #pragma unroll
            for (int kk = 0; kk < 4; kk++) {
                float wv[CT2];
                #pragma unroll
                for (int c = 0; c < CT2; c++) wv[c] = ws[(k4 * 4 + kk) * O + cb2 + 32 * c];
                #pragma unroll
                for (int r = 0; r < RT; r++) {
                    float hvk = (kk == 0) ? hv[r].x : (kk == 1) ? hv[r].y : (kk == 2) ? hv[r].z : hv[r].w;
                    #pragma unroll
                    for (int c = 0; c < CT2; c++)
                        acc2[r][c] = fmaf(hvk, wv[c], acc2[r][c]);
                }
            }
        }
        __syncthreads();
    }

    const int bat = row0 / RPB;
    #pragma unroll
    for (int c = 0; c < CT2; c++) {
        float bias = bb[cb2 + 32 * c];
        float pv   = p[bat * O + cb2 + 32 * c];
        #pragma unroll
        for (int r = 0; r < RT; r++) {
            float y = acc2[r][c] + bias;
            if (!PLAIN) y = ftanh(y);
            outp[(size_t)(row0 + rw * RT + r) * O + cb2 + 32 * c] = y * pv;
        }
    }
}

// -------- tail: append pos_skip_l0 and batch_skip_l0 (as float) --------
__global__ void tail_kernel(const float* __restrict__ pos0,
                            const int* __restrict__ bat0,
                            float* __restrict__ out)
{
    const int i = blockIdx.x * blockDim.x + threadIdx.x;
    const int NP = NT0 * 3;
    if (i < NP)
        out[(size_t)NT0 * O2 + i] = pos0[i];
    else if (i < NP + NT0)
        out[(size_t)NT0 * O2 + i] = (float)bat0[i - NP];
}

extern "C" void kernel_launch(void* const* d_in, const int* in_sizes, int n_in,
                              void* d_out, int out_size) {
    const float* par          = (const float*)d_in[0];
    const float* x            = (const float*)d_in[1];
    const float* pos          = (const float*)d_in[2];
    const float* x_skip_l1    = (const float*)d_in[4];
    const float* pos_skip_l1  = (const float*)d_in[5];
    const float* x_skip_l0    = (const float*)d_in[7];
    const float* pos_skip_l0  = (const float*)d_in[8];
    const int*   batch_skip_l0= (const int*)  d_in[9];
    const float* W0a = (const float*)d_in[10];
    const float* b0a = (const float*)d_in[11];
    const float* W0b = (const float*)d_in[12];
    const float* b0b = (const float*)d_in[13];
    const float* Wp0 = (const float*)d_in[14];
    const float* bp0 = (const float*)d_in[15];
    const float* W1a = (const float*)d_in[16];
    const float* b1a = (const float*)d_in[17];
    const float* W1b = (const float*)d_in[18];
    const float* b1b = (const float*)d_in[19];
    const float* Wp1 = (const float*)d_in[20];
    const float* bp1 = (const float*)d_in[21];
    float* out = (float*)d_out;

    const int smem1 = (32 * KD1 + 32 * H1 + 16 * H1) * sizeof(float);  // 98304
    const int smem2 = (64 * KD2 + 64 * H2 + 16 * H2) * sizeof(float);  // 90112
    cudaFuncSetAttribute(mlp_kernel<1>, cudaFuncAttributeMaxDynamicSharedMemorySize, smem1);
    cudaFuncSetAttribute(mlp_kernel<2>, cudaFuncAttributeMaxDynamicSharedMemorySize, smem2);

    par_kernel<<<1, 128>>>(par, Wp0, bp0, Wp1, bp1);

    knn_kernel<1><<<NT1 / 128, 128>>>(pos, pos_skip_l1);
    knn_kernel<2><<<NT0 / 128, 128>>>(pos_skip_l1, pos_skip_l0);

    mlp_kernel<1><<<NT1 / 32, 256, smem1>>>(W0a, b0a, W0b, b0b, x, x_skip_l1, nullptr);
    mlp_kernel<2><<<NT0 / 64, 256, smem2>>>(W1a, b1a, W1b, b1b, nullptr, x_skip_l0, out);

    const long long full = (long long)NT0 * O2 + (long long)NT0 * 3 + NT0;
    if ((long long)out_size >= full) {
        tail_kernel<<<(NT0 * 3 + NT0 + 255) / 256, 256>>>(pos_skip_l0, batch_skip_l0, out);
    }
}